// round 11
// baseline (speedup 1.0000x reference)
#include <cuda_runtime.h>
#include <cuda_fp16.h>
#include <math.h>
#include <stdint.h>

// Problem constants
#define BB   256
#define TT   512
#define DIN  64
#define HH   1024
#define DOUT 10

// Config: 128 CTAs (4 batch-tiles x 32 h-tiles), tile 64 batch x 32 h-out
#define GRID 128
#define NTH  256
#define BT   64
#define HT   32
#define KCH  64
#define NIB  4             // independent barrier groups (one per batch-tile)
#define IBW  32            // CTAs per ib-group

// SMEM: only B (Whh|Whx rows, padded stride) + bias. A fragments come via LDG.cg.
#define BSTRIDE_H 1096                     // halves per B row (1024 Whh + 64 Whx + 8 pad)
#define BSTRIDE_B (BSTRIDE_H*2)            // 2192 B == 4 mod 32 words -> conflict-free ldsm
#define SM_B      0
#define SM_B_SZ   (HT*BSTRIDE_B)           // 70144
#define SM_BIAS   SM_B_SZ
#define SMEM_BYTES (SM_BIAS + 128)         // 70272

#define SPIN_BOUND (1u<<20)

// Global scratch (__device__ globals: allocation-free rule)
__device__ __align__(256) __half g_h[2][BB][HH];    // double-buffered hidden state fp16
__device__ __align__(256) __half g_x[TT][BB][DIN];  // x pre-converted fp16, [t][b][d]
__device__ unsigned g_bar[TT][NIB];                 // per-step, per-ib-group barrier counters

// ---------------- helpers ----------------
__device__ __forceinline__ void ldsm_x4(uint32_t& r0, uint32_t& r1, uint32_t& r2, uint32_t& r3,
                                        uint32_t addr) {
    asm volatile("ldmatrix.sync.aligned.m8n8.x4.shared.b16 {%0,%1,%2,%3}, [%4];"
                 : "=r"(r0), "=r"(r1), "=r"(r2), "=r"(r3) : "r"(addr));
}

__device__ __forceinline__ void mma16816(float* c, const uint32_t* a, uint32_t b0, uint32_t b1) {
    asm volatile(
        "mma.sync.aligned.m16n8k16.row.col.f32.f16.f16.f32 "
        "{%0,%1,%2,%3}, {%4,%5,%6,%7}, {%8,%9}, {%0,%1,%2,%3};"
        : "+f"(c[0]), "+f"(c[1]), "+f"(c[2]), "+f"(c[3])
        : "r"(a[0]), "r"(a[1]), "r"(a[2]), "r"(a[3]), "r"(b0), "r"(b1));
}

__device__ __forceinline__ float tanh_fast(float x) {
    float e = __expf(2.0f * x);
    return 1.0f - __fdividef(2.0f, e + 1.0f);
}

// A-fragment direct load: chunk c, all 4 kk -> 16 regs. L2-only (.cg) because h is
// produced by other SMs each step (L1 would serve stale lines).
__device__ __forceinline__ void loadA16(unsigned* a, const unsigned* p0, const unsigned* p1,
                                        int c, int thr4) {
    #pragma unroll
    for (int kk = 0; kk < 4; ++kk) {
        const int idx = c*32 + kk*8 + thr4;
        a[kk*4+0] = __ldcg(p0 + idx);
        a[kk*4+1] = __ldcg(p1 + idx);
        a[kk*4+2] = __ldcg(p0 + idx + 4);
        a[kk*4+3] = __ldcg(p1 + idx + 4);
    }
}

// ---------------- init: zero state, convert x fp32->fp16 into [t][b][d] ----------------
__global__ void rnn_init_kernel(const float* __restrict__ x) {
    int i = blockIdx.x * blockDim.x + threadIdx.x;
    int stride = gridDim.x * blockDim.x;
    if (i < BB*HH) ((__half*)g_h)[i] = __ushort_as_half((unsigned short)0);
    if (i < TT*NIB) ((unsigned*)g_bar)[i] = 0u;
    for (int j = i; j < BB*TT*DIN; j += stride) {
        int d = j & 63;
        int t = (j >> 6) & 511;
        int b = j >> 15;
        g_x[t][b][d] = __float2half_rn(x[j]);
    }
}

// ---------------- persistent RNN kernel ----------------
__global__ void __launch_bounds__(NTH, 1)
rnn_hmma_kernel(const float* __restrict__ Whh, const float* __restrict__ Whx,
                const float* __restrict__ bh,  const float* __restrict__ Why,
                const float* __restrict__ by,  float* __restrict__ out)
{
    extern __shared__ char sm[];
    const uint32_t smb = (uint32_t)__cvta_generic_to_shared(sm);
    const int tid = threadIdx.x, warp = tid >> 5, lane = tid & 31;
    const int cta = blockIdx.x;
    const int jb = cta & 31, ib = cta >> 5;    // 32 h-tiles x 4 b-tiles
    const int h_base = jb * HT;
    const int b_base = ib * BT;

    // ---- stage B once: Whh [32,1024] + Whx [32,64] as fp16 rows of stride 1096 ----
    __half* bs = (__half*)(sm + SM_B);
    for (int i = tid; i < HT*HH/2; i += NTH) {
        int n = i >> 9, k = (i & 511) * 2;
        const float* src = &Whh[(size_t)(h_base + n)*HH + k];
        *(__half2*)&bs[n*BSTRIDE_H + k] = __floats2half2_rn(src[0], src[1]);
    }
    for (int i = tid; i < HT*DIN/2; i += NTH) {
        int n = i >> 5, k = (i & 31) * 2;
        *(__half2*)&bs[n*BSTRIDE_H + 1024 + k] =
            __floats2half2_rn(Whx[(h_base + n)*DIN + k], Whx[(h_base + n)*DIN + k + 1]);
    }
    float* bias_s = (float*)(sm + SM_BIAS);
    if (tid < HT) bias_s[tid] = bh[h_base + tid];
    __syncthreads();

    // warp tiling: 4 m-warps (16 rows each) x 2 n-warps (16 cols each)
    const int wm   = (warp >> 1) * 16;
    const int wn   = (warp & 1) * 16;
    const int grp  = lane >> 2, thr4 = lane & 3;

    // B ldmatrix lane addressing (unchanged from R10)
    const int b_row  = wn + (lane & 7) + 8*(lane >> 4);
    const int b_koff = 8 * ((lane >> 3) & 1);
    const uint32_t b_lane = smb + SM_B + b_row*BSTRIDE_B + b_koff*2;

    // A fragment rows for this lane
    const int r0 = b_base + wm + grp;          // and r0+8

    bool alive = true;

    for (int t = 0; t < TT; ++t) {
        const unsigned* hp0 = (const unsigned*)&g_h[t & 1][r0][0];     // 512 u32/row
        const unsigned* hp1 = hp0 + 8*512;
        const unsigned* xp0 = (const unsigned*)&g_x[t][r0][0];         // 32 u32/row
        const unsigned* xp1 = xp0 + 8*32;

        // ---- prefetch x fragments (h-independent) BEFORE the barrier wait ----
        unsigned ax[16];
        #pragma unroll
        for (int kk = 0; kk < 4; ++kk) {
            const int idx = kk*8 + thr4;
            ax[kk*4+0] = __ldcg(xp0 + idx);
            ax[kk*4+1] = __ldcg(xp1 + idx);
            ax[kk*4+2] = __ldcg(xp0 + idx + 4);
            ax[kk*4+3] = __ldcg(xp1 + idx + 4);
        }

        // ---- wait for h_t ready: only the 32 CTAs of our ib-group matter ----
        if (t > 0) {
            if (tid == 0 && alive) {
                unsigned spins = 0;
                while (*((volatile unsigned*)&g_bar[t-1][ib]) < IBW) {
                    if (++spins >= SPIN_BOUND) { alive = false; break; }
                    __nanosleep(8);
                }
            }
            __threadfence();
            __syncthreads();
        }

        // split accumulators: even kk -> A set, odd kk -> B set (breaks mma dep chain)
        float acc0a[4] = {0.f,0.f,0.f,0.f}, acc0b[4] = {0.f,0.f,0.f,0.f};
        float acc1a[4] = {0.f,0.f,0.f,0.f}, acc1b[4] = {0.f,0.f,0.f,0.f};

        auto mma_chunk = [&](const unsigned* areg, int c) {
            const uint32_t bbase = b_lane + c * 128;
            #pragma unroll
            for (int kk = 0; kk < 4; ++kk) {
                uint32_t b0,b1,b2,b3;
                ldsm_x4(b0,b1,b2,b3, bbase + kk*32);
                const unsigned* a = areg + kk*4;
                if (kk & 1) { mma16816(acc0b, a, b0, b1); mma16816(acc1b, a, b2, b3); }
                else        { mma16816(acc0a, a, b0, b1); mma16816(acc1a, a, b2, b3); }
            }
        };

        // ---- 16 h chunks, direct-LDG A with one-chunk lookahead; then x chunk ----
        unsigned ab[2][16];
        loadA16(ab[0], hp0, hp1, 0, thr4);
        #pragma unroll
        for (int c = 0; c < 16; ++c) {
            if (c + 1 < 16) loadA16(ab[(c+1) & 1], hp0, hp1, c+1, thr4);
            mma_chunk(ab[c & 1], c);
        }
        mma_chunk(ax, 16);     // x contribution (B cols 1024..1087)

        // ---- epilogue: combine accs, bias + tanh, store h_new fp16 ----
        {
            __half* hdst = &g_h[(t + 1) & 1][0][0];
            #pragma unroll
            for (int tile = 0; tile < 2; ++tile) {
                const float* aa = tile ? acc1a : acc0a;
                const float* abv = tile ? acc1b : acc0b;
                const int col = h_base + wn + tile*8 + 2*thr4;
                float bl  = bias_s[wn + tile*8 + 2*thr4];
                float bhp = bias_s[wn + tile*8 + 2*thr4 + 1];
                __half2 v0 = __floats2half2_rn(tanh_fast(aa[0] + abv[0] + bl),
                                               tanh_fast(aa[1] + abv[1] + bhp));
                __half2 v1 = __floats2half2_rn(tanh_fast(aa[2] + abv[2] + bl),
                                               tanh_fast(aa[3] + abv[3] + bhp));
                *(__half2*)&hdst[(size_t)r0*HH + col]     = v0;
                *(__half2*)&hdst[(size_t)(r0+8)*HH + col] = v1;
            }
        }

        // ---- arrive at our ib-group barrier (wait happens next iteration) ----
        __threadfence();
        __syncthreads();
        if (tid == 0) atomicAdd(&g_bar[t][ib], 1u);
    }

    // ---- wait for final h of the ib-group that owns our output rows ----
    {
        const int ib_read = (2*cta) >> 6;
        if (tid == 0 && alive) {
            unsigned spins = 0;
            while (*((volatile unsigned*)&g_bar[TT-1][ib_read]) < IBW) {
                if (++spins >= SPIN_BOUND) { alive = false; break; }
                __nanosleep(8);
            }
        }
        __threadfence();
        __syncthreads();
    }

    // ---- output: o = h_final @ Why^T + by, softmax over 10 (2 batch rows per CTA) ----
    float* logits = (float*)sm;            // mainloop smem dead now
    const __half* hf = &g_h[0][0][0];      // TT even -> final h in buffer 0
    for (int d = warp; d < 2*DOUT; d += 8) {
        int row = d / DOUT, col = d % DOUT;
        int b = 2*cta + row;
        const __half* hp = hf + (size_t)b*HH;
        const float* wpw = Why + (size_t)col*HH;
        float s = 0.f;
        for (int k = lane; k < HH; k += 32) {
            unsigned short hv = __ldcg((const unsigned short*)(hp + k));
            s += __half2float(__ushort_as_half(hv)) * wpw[k];
        }
        #pragma unroll
        for (int o = 16; o; o >>= 1) s += __shfl_down_sync(0xffffffffu, s, o);
        if (lane == 0) logits[d] = s + by[col];
    }
    __syncthreads();
    if (tid < 2) {
        int b = 2*cta + tid;
        float mx = -1e30f;
        for (int c = 0; c < DOUT; ++c) mx = fmaxf(mx, logits[tid*DOUT + c]);
        float e[DOUT], sum = 0.f;
        for (int c = 0; c < DOUT; ++c) { e[c] = expf(logits[tid*DOUT + c] - mx); sum += e[c]; }
        float inv = 1.f / sum;
        for (int c = 0; c < DOUT; ++c) out[b*DOUT + c] = e[c]*inv;
    }
}

extern "C" void kernel_launch(void* const* d_in, const int* in_sizes, int n_in,
                              void* d_out, int out_size) {
    const float* x   = (const float*)d_in[0];
    const float* Whx = (const float*)d_in[1];
    const float* Whh = (const float*)d_in[2];
    const float* bh  = (const float*)d_in[3];
    const float* Why = (const float*)d_in[4];
    const float* by  = (const float*)d_in[5];
    float* out = (float*)d_out;

    cudaFuncSetAttribute(rnn_hmma_kernel,
                         cudaFuncAttributeMaxDynamicSharedMemorySize, SMEM_BYTES);

    rnn_init_kernel<<<4096, 256>>>(x);
    rnn_hmma_kernel<<<GRID, NTH, SMEM_BYTES>>>(Whh, Whx, bh, Why, by, out);
}

// round 12
// speedup vs baseline: 2.1251x; 2.1251x over previous
#include <cuda_runtime.h>
#include <cuda_fp16.h>
#include <math.h>
#include <stdint.h>

// Problem constants
#define BB   256
#define TT   512
#define DIN  64
#define HH   1024
#define DOUT 10

// Config: 128 CTAs (4 batch-tiles x 32 h-tiles), tile 64 batch x 32 h-out.
// 512 threads: K-split — half 0 (warps 0-7): x + chunks 0..7; half 1: chunks 8..15.
#define GRID 128
#define NTH  512
#define BT   64
#define HT   32
#define KCH  64
#define NCH  17            // 16 h-chunks + 1 x-chunk
#define NIB  4
#define IBW  32

// SMEM layout (bytes). Strides padded so 8-row ldmatrix groups hit distinct banks.
#define BSTRIDE_H 1096                     // halves per Whh row (1024 + 64 Whx + 8 pad)
#define BSTRIDE_B (BSTRIDE_H*2)            // 2192 B == 4 mod 32 words
#define ASTRIDE_H 72                       // halves per A row (64 + 8 pad)
#define ASTRIDE_B (ASTRIDE_H*2)            // 144 B
#define ABUF_B    (BT*ASTRIDE_B)           // 9216 B per chunk buffer
#define SM_B      0
#define SM_B_SZ   (HT*BSTRIDE_B)           // 70144
#define SM_A      SM_B_SZ
#define SM_A_SZ   (NCH*ABUF_B)             // 156672
#define SM_BIAS   (SM_A + SM_A_SZ)         // 226816
#define SMEM_BYTES (SM_BIAS + 128)         // 226944
// Reduction region overlays buffer 15 (half-1's last chunk; per-pair row ranges)
#define SM_RED    (SM_A + 15*ABUF_B)

#define SPIN_BOUND (1u<<20)

// Global scratch (__device__ globals: allocation-free rule)
__device__ __align__(256) __half g_h[2][BB][HH];
__device__ __align__(256) __half g_x[TT][BB][DIN];
__device__ unsigned g_bar[TT][NIB];

// ---------------- helpers ----------------
__device__ __forceinline__ void cp_async16(void* sptr, const void* gptr) {
    uint32_t s = (uint32_t)__cvta_generic_to_shared(sptr);
    asm volatile("cp.async.cg.shared.global [%0], [%1], 16;" :: "r"(s), "l"(gptr));
}
__device__ __forceinline__ void cp_commit() { asm volatile("cp.async.commit_group;"); }
template<int N> __device__ __forceinline__ void cp_wait() {
    asm volatile("cp.async.wait_group %0;" :: "n"(N));
}
__device__ __forceinline__ void cp_wait_dyn(int n) {
    switch (n) {
    case 0: cp_wait<0>(); break; case 1: cp_wait<1>(); break;
    case 2: cp_wait<2>(); break; case 3: cp_wait<3>(); break;
    case 4: cp_wait<4>(); break; case 5: cp_wait<5>(); break;
    case 6: cp_wait<6>(); break; case 7: cp_wait<7>(); break;
    default: cp_wait<8>(); break;
    }
}

__device__ __forceinline__ void ldsm_x4(uint32_t& r0, uint32_t& r1, uint32_t& r2, uint32_t& r3,
                                        uint32_t addr) {
    asm volatile("ldmatrix.sync.aligned.m8n8.x4.shared.b16 {%0,%1,%2,%3}, [%4];"
                 : "=r"(r0), "=r"(r1), "=r"(r2), "=r"(r3) : "r"(addr));
}

__device__ __forceinline__ void mma16816(float* c, const uint32_t* a, uint32_t b0, uint32_t b1) {
    asm volatile(
        "mma.sync.aligned.m16n8k16.row.col.f32.f16.f16.f32 "
        "{%0,%1,%2,%3}, {%4,%5,%6,%7}, {%8,%9}, {%0,%1,%2,%3};"
        : "+f"(c[0]), "+f"(c[1]), "+f"(c[2]), "+f"(c[3])
        : "r"(a[0]), "r"(a[1]), "r"(a[2]), "r"(a[3]), "r"(b0), "r"(b1));
}

__device__ __forceinline__ float tanh_fast(float x) {
    float e = __expf(2.0f * x);
    return 1.0f - __fdividef(2.0f, e + 1.0f);
}

// ---------------- init ----------------
__global__ void rnn_init_kernel(const float* __restrict__ x) {
    int i = blockIdx.x * blockDim.x + threadIdx.x;
    int stride = gridDim.x * blockDim.x;
    if (i < BB*HH) ((__half*)g_h)[i] = __ushort_as_half((unsigned short)0);
    if (i < TT*NIB) ((unsigned*)g_bar)[i] = 0u;
    for (int j = i; j < BB*TT*DIN; j += stride) {
        int d = j & 63;
        int t = (j >> 6) & 511;
        int b = j >> 15;
        g_x[t][b][d] = __float2half_rn(x[j]);
    }
}

// ---------------- persistent RNN kernel ----------------
__global__ void __launch_bounds__(NTH, 1)
rnn_hmma_kernel(const float* __restrict__ Whh, const float* __restrict__ Whx,
                const float* __restrict__ bh,  const float* __restrict__ Why,
                const float* __restrict__ by,  float* __restrict__ out)
{
    extern __shared__ char sm[];
    const uint32_t smb = (uint32_t)__cvta_generic_to_shared(sm);
    const int tid = threadIdx.x, warp = tid >> 5, lane = tid & 31;
    const int cta = blockIdx.x;
    const int jb = cta & 31, ib = cta >> 5;
    const int h_base = jb * HT;
    const int b_base = ib * BT;

    // ---- stage B once ----
    __half* bs = (__half*)(sm + SM_B);
    for (int i = tid; i < HT*HH/2; i += NTH) {
        int n = i >> 9, k = (i & 511) * 2;
        const float* src = &Whh[(size_t)(h_base + n)*HH + k];
        *(__half2*)&bs[n*BSTRIDE_H + k] = __floats2half2_rn(src[0], src[1]);
    }
    for (int i = tid; i < HT*DIN/2; i += NTH) {
        int n = i >> 5, k = (i & 31) * 2;
        *(__half2*)&bs[n*BSTRIDE_H + 1024 + k] =
            __floats2half2_rn(Whx[(h_base + n)*DIN + k], Whx[(h_base + n)*DIN + k + 1]);
    }
    float* bias_s = (float*)(sm + SM_BIAS);
    if (tid < HT) bias_s[tid] = bh[h_base + tid];
    __syncthreads();

    // warp decomposition: half (K-split), 4 m-pairs x 2 n-warps per half
    const int half = warp >> 3;
    const int wl   = warp & 7;
    const int wp   = wl >> 1;            // m-tile 0..3
    const int wm   = wp * 16;
    const int wn   = (wl & 1) * 16;
    const int grp  = lane >> 2, thr4 = lane & 3;
    const int barid = 1 + half*4 + wp;   // 8 named barriers, 64 threads each
    const int ptid = tid & 63;           // pair-local tid (warps 2m,2m+1 contiguous)

    // ldmatrix lane addressing
    const int a_row  = wm + (lane & 7) + 8*((lane >> 3) & 1);
    const int a_koff = 8 * (lane >> 4);
    const int b_row  = wn + (lane & 7) + 8*(lane >> 4);
    const int b_koff = 8 * ((lane >> 3) & 1);
    const uint32_t a_lane = smb + SM_A + a_row*ASTRIDE_B + a_koff*2;
    const uint32_t b_lane = smb + SM_B + b_row*BSTRIDE_B + b_koff*2;

    // staging: thread handles rows (sr, sr+8), 16B unit sq, for its half's chunks
    const int sr = wm + (ptid >> 3);
    const int sq = ptid & 7;
    char* const sa0 = sm + SM_A + sr*ASTRIDE_B + sq*16;
    char* const sa1 = sm + SM_A + (sr+8)*ASTRIDE_B + sq*16;

    // reduction region for this (m,n) tile: inside buffer 15, pair-m's rows
    float* const red = (float*)(sm + SM_RED + wp*(16*ASTRIDE_B) + (wl & 1)*1024);

    bool alive = true;

    for (int t = 0; t < TT; ++t) {
        const __half* hsrc = &g_h[t & 1][0][0];

        // ---- half 0: stage x chunk (h-independent) BEFORE the barrier wait ----
        if (half == 0) {
            const __half* s0 = &g_x[t][b_base + sr][sq*8];
            cp_async16(sa0 + 16*ABUF_B, s0);
            cp_async16(sa1 + 16*ABUF_B, s0 + 8*DIN);
            cp_commit();
        }

        // ---- wait for h_t ready (our ib-group only) ----
        if (t > 0) {
            if (tid == 0 && alive) {
                unsigned spins = 0;
                while (*((volatile unsigned*)&g_bar[t-1][ib]) < IBW) {
                    if (++spins >= SPIN_BOUND) { alive = false; break; }
                    __nanosleep(8);
                }
            }
            __threadfence();
            __syncthreads();
        }

        // ---- stage this half's h chunks (one cp.async group each) ----
        {
            const __half* h0 = hsrc + (size_t)(b_base + sr)*HH + sq*8;
            const __half* h1 = hsrc + (size_t)(b_base + sr + 8)*HH + sq*8;
            const int c0 = half * 8;
            #pragma unroll
            for (int e = 0; e < 8; ++e) {
                const int c = c0 + e;
                cp_async16(sa0 + c*ABUF_B, h0 + c*KCH);
                cp_async16(sa1 + c*ABUF_B, h1 + c*KCH);
                cp_commit();
            }
        }

        float acc0a[4] = {0.f,0.f,0.f,0.f}, acc0b[4] = {0.f,0.f,0.f,0.f};
        float acc1a[4] = {0.f,0.f,0.f,0.f}, acc1b[4] = {0.f,0.f,0.f,0.f};

        auto do_chunk = [&](int c) {
            const uint32_t abase = a_lane + c * ABUF_B;
            const uint32_t bbase = b_lane + c * (KCH * 2);
            #pragma unroll
            for (int kk = 0; kk < 4; ++kk) {
                uint32_t a0,a1,a2,a3, b0,b1,b2,b3;
                ldsm_x4(a0,a1,a2,a3, abase + kk*32);
                ldsm_x4(b0,b1,b2,b3, bbase + kk*32);
                uint32_t a[4] = {a0,a1,a2,a3};
                if (kk & 1) { mma16816(acc0b, a, b0, b1); mma16816(acc1b, a, b2, b3); }
                else        { mma16816(acc0a, a, b0, b1); mma16816(acc1a, a, b2, b3); }
            }
        };

        if (half == 0) {
            // x chunk landed first (it is the oldest of our 9 groups)
            cp_wait<8>();
            asm volatile("bar.sync %0, 64;" :: "r"(barid) : "memory");
            do_chunk(16);
            #pragma unroll
            for (int c = 0; c < 8; ++c) {
                cp_wait_dyn(7 - c);
                asm volatile("bar.sync %0, 64;" :: "r"(barid) : "memory");
                do_chunk(c);
            }
        } else {
            #pragma unroll
            for (int c = 8; c < 16; ++c) {
                cp_wait_dyn(15 - c);
                asm volatile("bar.sync %0, 64;" :: "r"(barid) : "memory");
                do_chunk(c);
            }
            // both warps of the pair must finish READING buffer 15 before either
            // overwrites it with partials
            asm volatile("bar.sync %0, 64;" :: "r"(barid) : "memory");
            #pragma unroll
            for (int tile = 0; tile < 2; ++tile) {
                const float* aa = tile ? acc1a : acc0a;
                const float* ab = tile ? acc1b : acc0b;
                const int col = tile*8 + 2*thr4;
                *(float2*)&red[grp*16 + col]     = make_float2(aa[0]+ab[0], aa[1]+ab[1]);
                *(float2*)&red[(grp+8)*16 + col] = make_float2(aa[2]+ab[2], aa[3]+ab[3]);
            }
        }

        __syncthreads();   // partials visible; all A buffers dead

        // ---- epilogue (half 0): combine halves, bias + tanh, store h_new ----
        if (half == 0) {
            __half* hdst = &g_h[(t + 1) & 1][0][0];
            const int r0 = b_base + wm + grp;
            #pragma unroll
            for (int tile = 0; tile < 2; ++tile) {
                const float* aa = tile ? acc1a : acc0a;
                const float* ab = tile ? acc1b : acc0b;
                const int lcol = wn + tile*8 + 2*thr4;
                const int col = h_base + lcol;
                float2 p0 = *(float2*)&red[grp*16 + tile*8 + 2*thr4];
                float2 p1 = *(float2*)&red[(grp+8)*16 + tile*8 + 2*thr4];
                float bl  = bias_s[lcol];
                float bhp = bias_s[lcol + 1];
                __half2 v0 = __floats2half2_rn(tanh_fast(aa[0]+ab[0]+p0.x + bl),
                                               tanh_fast(aa[1]+ab[1]+p0.y + bhp));
                __half2 v1 = __floats2half2_rn(tanh_fast(aa[2]+ab[2]+p1.x + bl),
                                               tanh_fast(aa[3]+ab[3]+p1.y + bhp));
                *(__half2*)&hdst[(size_t)r0*HH + col]     = v0;
                *(__half2*)&hdst[(size_t)(r0+8)*HH + col] = v1;
            }
        }

        // ---- arrive at our ib-group barrier ----
        __threadfence();
        __syncthreads();
        if (tid == 0) atomicAdd(&g_bar[t][ib], 1u);
    }

    // ---- wait for final h of the ib-group that owns our output rows ----
    {
        const int ib_read = (2*cta) >> 6;
        if (tid == 0 && alive) {
            unsigned spins = 0;
            while (*((volatile unsigned*)&g_bar[TT-1][ib_read]) < IBW) {
                if (++spins >= SPIN_BOUND) { alive = false; break; }
                __nanosleep(8);
            }
        }
        __threadfence();
        __syncthreads();
    }

    // ---- output: o = h_final @ Why^T + by, softmax (2 batch rows per CTA) ----
    float* logits = (float*)sm;
    const __half* hf = &g_h[0][0][0];
    for (int d = warp; d < 2*DOUT; d += 16) {
        int row = d / DOUT, col = d % DOUT;
        int b = 2*cta + row;
        const __half* hp = hf + (size_t)b*HH;
        const float* wpw = Why + (size_t)col*HH;
        float s = 0.f;
        for (int k = lane; k < HH; k += 32)
            s += __half2float(hp[k]) * wpw[k];
        #pragma unroll
        for (int o = 16; o; o >>= 1) s += __shfl_down_sync(0xffffffffu, s, o);
        if (lane == 0) logits[d] = s + by[col];
    }
    __syncthreads();
    if (tid < 2) {
        int b = 2*cta + tid;
        float mx = -1e30f;
        for (int c = 0; c < DOUT; ++c) mx = fmaxf(mx, logits[tid*DOUT + c]);
        float e[DOUT], sum = 0.f;
        for (int c = 0; c < DOUT; ++c) { e[c] = expf(logits[tid*DOUT + c] - mx); sum += e[c]; }
        float inv = 1.f / sum;
        for (int c = 0; c < DOUT; ++c) out[b*DOUT + c] = e[c]*inv;
    }
}

extern "C" void kernel_launch(void* const* d_in, const int* in_sizes, int n_in,
                              void* d_out, int out_size) {
    const float* x   = (const float*)d_in[0];
    const float* Whx = (const float*)d_in[1];
    const float* Whh = (const float*)d_in[2];
    const float* bh  = (const float*)d_in[3];
    const float* Why = (const float*)d_in[4];
    const float* by  = (const float*)d_in[5];
    float* out = (float*)d_out;

    cudaFuncSetAttribute(rnn_hmma_kernel,
                         cudaFuncAttributeMaxDynamicSharedMemorySize, SMEM_BYTES);

    rnn_init_kernel<<<4096, 256>>>(x);
    rnn_hmma_kernel<<<GRID, NTH, SMEM_BYTES>>>(Whh, Whx, bh, Why, by, out);
}

// round 13
// speedup vs baseline: 2.2745x; 1.0703x over previous
#include <cuda_runtime.h>
#include <cuda_fp16.h>
#include <math.h>
#include <stdint.h>

// Problem constants
#define BB   256
#define TT   512
#define DIN  64
#define HH   1024
#define DOUT 10

// Config: 64 CTAs (4 batch-tiles x 16 h-tiles), tile 64 batch x 64 h-out.
// 256 threads = 2 K-split halves x 4 warps; warp tile 32x32.
#define GRID 64
#define NTH  256
#define BT   64
#define HT   64
#define KCH  64
#define NIB  4
#define IBW  16

// SMEM layout (bytes)
#define BSTRIDE_H 1096                     // halves per B row (1024 Whh + 64 Whx + 8 pad)
#define BSTRIDE_B (BSTRIDE_H*2)            // 2192 == 4 mod 32 words -> conflict-free ldsm
#define ASTRIDE_B 144                      // A row stride (64 halves + pad)
#define ABUF_B    (BT*ASTRIDE_B)           // 9216 per chunk buffer
#define SM_B      0
#define SM_B_SZ   (HT*BSTRIDE_B)           // 140288
#define SM_A0     SM_B_SZ                  // half0 ring: 4 bufs
#define SM_AX     (SM_A0 + 4*ABUF_B)       // x buffer
#define SM_A1     (SM_AX + ABUF_B)         // half1 ring: 4 bufs
#define SM_RED    SM_A1                    // reduction overlays half1 bufs 0,1 (16KB<18.4KB)
#define SM_BIAS   (SM_A1 + 4*ABUF_B)       // 223232
#define SMEM_BYTES (SM_BIAS + 256)         // 223488 (< 232448 cap)

#define SPIN_BOUND (1u<<20)

// Global scratch (__device__ globals: allocation-free rule)
__device__ __align__(256) __half g_h[2][BB][HH];
__device__ __align__(256) __half g_x[TT][BB][DIN];
__device__ unsigned g_bar[TT][NIB];

// ---------------- helpers ----------------
__device__ __forceinline__ void cp_async16(void* sptr, const void* gptr) {
    uint32_t s = (uint32_t)__cvta_generic_to_shared(sptr);
    asm volatile("cp.async.cg.shared.global [%0], [%1], 16;" :: "r"(s), "l"(gptr));
}
__device__ __forceinline__ void cp_commit() { asm volatile("cp.async.commit_group;"); }
template<int N> __device__ __forceinline__ void cp_wait() {
    asm volatile("cp.async.wait_group %0;" :: "n"(N));
}
__device__ __forceinline__ void cp_wait_dyn(int n) {
    switch (n) {
    case 0: cp_wait<0>(); break; case 1: cp_wait<1>(); break;
    case 2: cp_wait<2>(); break; case 3: cp_wait<3>(); break;
    default: cp_wait<4>(); break;
    }
}

__device__ __forceinline__ void ldsm_x4(uint32_t& r0, uint32_t& r1, uint32_t& r2, uint32_t& r3,
                                        uint32_t addr) {
    asm volatile("ldmatrix.sync.aligned.m8n8.x4.shared.b16 {%0,%1,%2,%3}, [%4];"
                 : "=r"(r0), "=r"(r1), "=r"(r2), "=r"(r3) : "r"(addr));
}

__device__ __forceinline__ void mma16816(float* c, const uint32_t* a, uint32_t b0, uint32_t b1) {
    asm volatile(
        "mma.sync.aligned.m16n8k16.row.col.f32.f16.f16.f32 "
        "{%0,%1,%2,%3}, {%4,%5,%6,%7}, {%8,%9}, {%0,%1,%2,%3};"
        : "+f"(c[0]), "+f"(c[1]), "+f"(c[2]), "+f"(c[3])
        : "r"(a[0]), "r"(a[1]), "r"(a[2]), "r"(a[3]), "r"(b0), "r"(b1));
}

__device__ __forceinline__ float tanh_fast(float x) {
    float e = __expf(2.0f * x);
    return 1.0f - __fdividef(2.0f, e + 1.0f);
}

// ---------------- init ----------------
__global__ void rnn_init_kernel(const float* __restrict__ x) {
    int i = blockIdx.x * blockDim.x + threadIdx.x;
    int stride = gridDim.x * blockDim.x;
    if (i < BB*HH) ((__half*)g_h)[i] = __ushort_as_half((unsigned short)0);
    if (i < TT*NIB) ((unsigned*)g_bar)[i] = 0u;
    for (int j = i; j < BB*TT*DIN; j += stride) {
        int d = j & 63;
        int t = (j >> 6) & 511;
        int b = j >> 15;
        g_x[t][b][d] = __float2half_rn(x[j]);
    }
}

// ---------------- persistent RNN kernel ----------------
__global__ void __launch_bounds__(NTH, 1)
rnn_hmma_kernel(const float* __restrict__ Whh, const float* __restrict__ Whx,
                const float* __restrict__ bh,  const float* __restrict__ Why,
                const float* __restrict__ by,  float* __restrict__ out)
{
    extern __shared__ char sm[];
    const uint32_t smb = (uint32_t)__cvta_generic_to_shared(sm);
    const int tid = threadIdx.x, warp = tid >> 5, lane = tid & 31;
    const int cta = blockIdx.x;
    const int jb = cta & 15, ib = cta >> 4;    // 16 h-tiles x 4 b-tiles
    const int h_base = jb * HT;
    const int b_base = ib * BT;

    // ---- stage B once: Whh [64,1024] + Whx [64,64] fp16, row stride 1096 halves ----
    __half* bs = (__half*)(sm + SM_B);
    for (int i = tid; i < HT*HH/2; i += NTH) {
        int n = i >> 9, k = (i & 511) * 2;
        const float* src = &Whh[(size_t)(h_base + n)*HH + k];
        *(__half2*)&bs[n*BSTRIDE_H + k] = __floats2half2_rn(src[0], src[1]);
    }
    for (int i = tid; i < HT*DIN/2; i += NTH) {
        int n = i >> 5, k = (i & 31) * 2;
        *(__half2*)&bs[n*BSTRIDE_H + 1024 + k] =
            __floats2half2_rn(Whx[(h_base + n)*DIN + k], Whx[(h_base + n)*DIN + k + 1]);
    }
    float* bias_s = (float*)(sm + SM_BIAS);
    if (tid < HT) bias_s[tid] = bh[h_base + tid];
    __syncthreads();

    // warp decomposition: half (K-split) x [2m x 2n] 32x32 warp tiles
    const int half = warp >> 2;
    const int wq   = warp & 3;
    const int wm   = (wq >> 1) * 32;
    const int wn   = (wq & 1) * 32;
    const int grp  = lane >> 2, thr4 = lane & 3;
    const int barid = 1 + half;
    const int ptid = tid & 127;

    // ldsm lane addressing
    const int a_r = (lane & 7) + 8*((lane >> 3) & 1);
    const uint32_t a_rel = (uint32_t)((wm + a_r)*ASTRIDE_B + (lane >> 4)*16);
    const int b_r = (lane & 7) + 8*(lane >> 4);
    const uint32_t b_k2 = (uint32_t)(((lane >> 3) & 1) * 16);
    const uint32_t bB0 = smb + SM_B + (uint32_t)((wn + b_r)*BSTRIDE_B) + b_k2;
    const uint32_t bB1 = bB0 + 16*BSTRIDE_B;

    // staging: 128 threads of a half stage 64 rows x 8 16B-units (4 ops/thread/chunk)
    const int srow = ptid >> 3;
    const int sq   = ptid & 7;

    char* const pA0 = sm + SM_A0;
    char* const pAX = sm + SM_AX;
    char* const pA1 = sm + SM_A1;
    const uint32_t A0 = smb + SM_A0, AX = smb + SM_AX, A1 = smb + SM_A1;

    float acc[2][2][2][4];

    auto stage4 = [&](char* dst, const __half* src, int sstride) {
        #pragma unroll
        for (int rr = 0; rr < 4; ++rr) {
            int r = srow + rr*16;
            cp_async16(dst + r*ASTRIDE_B + sq*16, src + (size_t)r*sstride + sq*8);
        }
        cp_commit();
    };

    auto do_chunk = [&](uint32_t abuf, int c) {
        const uint32_t bc = (uint32_t)(c * 128);
        #pragma unroll
        for (int kk = 0; kk < 4; ++kk) {
            uint32_t a0[4], a1[4], b0[4], b1[4];
            ldsm_x4(a0[0],a0[1],a0[2],a0[3], abuf + a_rel + kk*32);
            ldsm_x4(a1[0],a1[1],a1[2],a1[3], abuf + a_rel + 16*ASTRIDE_B + kk*32);
            ldsm_x4(b0[0],b0[1],b0[2],b0[3], bB0 + bc + kk*32);
            ldsm_x4(b1[0],b1[1],b1[2],b1[3], bB1 + bc + kk*32);
            mma16816(acc[0][0][0], a0, b0[0], b0[1]);
            mma16816(acc[0][0][1], a0, b0[2], b0[3]);
            mma16816(acc[0][1][0], a0, b1[0], b1[1]);
            mma16816(acc[0][1][1], a0, b1[2], b1[3]);
            mma16816(acc[1][0][0], a1, b0[0], b0[1]);
            mma16816(acc[1][0][1], a1, b0[2], b0[3]);
            mma16816(acc[1][1][0], a1, b1[0], b1[1]);
            mma16816(acc[1][1][1], a1, b1[2], b1[3]);
        }
    };

    bool alive = true;

    for (int t = 0; t < TT; ++t) {
        const __half* hsrc = &g_h[t & 1][0][0];
        const __half* hrow = hsrc + (size_t)b_base*HH;

        // half0: stage x chunk (h-independent) before the barrier wait
        if (half == 0) stage4(pAX, &g_x[t][b_base][0], DIN);

        // ---- wait for h_t (our 16-CTA ib-group only); single-thread acquire fence ----
        if (t > 0) {
            if (tid == 0) {
                if (alive) {
                    unsigned spins = 0;
                    while (*((volatile unsigned*)&g_bar[t-1][ib]) < IBW) {
                        if (++spins >= SPIN_BOUND) { alive = false; break; }
                        __nanosleep(8);
                    }
                }
                __threadfence();
            }
            __syncthreads();
        }

        #pragma unroll
        for (int i = 0; i < 2; ++i)
            #pragma unroll
            for (int j = 0; j < 2; ++j)
                #pragma unroll
                for (int k = 0; k < 2; ++k)
                    #pragma unroll
                    for (int q = 0; q < 4; ++q) acc[i][j][k][q] = 0.f;

        if (half == 0) {
            // ring prologue: h chunks 0..3
            #pragma unroll
            for (int p = 0; p < 4; ++p)
                stage4(pA0 + p*ABUF_B, hrow + p*KCH, HH);
            // x first (oldest group)
            cp_wait<4>();
            asm volatile("bar.sync %0, 128;" :: "r"(barid) : "memory");
            do_chunk(AX, 16);
            // h chunks 0..7; stage c+3 at iters 1..4 (chunks 4..7)
            #pragma unroll
            for (int c = 0; c < 8; ++c) {
                cp_wait_dyn((c == 0) ? 3 : ((c < 6) ? 2 : (7 - c)));
                asm volatile("bar.sync %0, 128;" :: "r"(barid) : "memory");
                if (c >= 1 && c <= 4)
                    stage4(pA0 + ((c+3) & 3)*ABUF_B, hrow + (c+3)*KCH, HH);
                do_chunk(A0 + (c & 3)*ABUF_B, c);
            }
        } else {
            // ring prologue: h chunks 8..11
            #pragma unroll
            for (int p = 0; p < 4; ++p)
                stage4(pA1 + p*ABUF_B, hrow + (8 + p)*KCH, HH);
            #pragma unroll
            for (int e = 0; e < 8; ++e) {
                cp_wait_dyn((e == 0) ? 3 : ((e < 6) ? 2 : (7 - e)));
                asm volatile("bar.sync %0, 128;" :: "r"(barid) : "memory");
                if (e >= 1 && e <= 4)
                    stage4(pA1 + ((e+3) & 3)*ABUF_B, hrow + (11 + e)*KCH, HH);
                do_chunk(A1 + (e & 3)*ABUF_B, 8 + e);
            }
            // all half1 warps done reading ring before overwriting with partials
            asm volatile("bar.sync %0, 128;" :: "r"(barid) : "memory");
            char* red = sm + SM_RED + wq*4096;
            #pragma unroll
            for (int s_m = 0; s_m < 2; ++s_m)
                #pragma unroll
                for (int sn = 0; sn < 2; ++sn)
                    #pragma unroll
                    for (int j = 0; j < 2; ++j)
                        *(float4*)(red + (((s_m*2 + sn)*2 + j)*512) + lane*16) =
                            *(float4*)acc[s_m][sn][j];
        }

        __syncthreads();   // partials visible; half0 compute done

        if (half == 0) {
            char* red = sm + SM_RED + wq*4096;
            __half* hdst = &g_h[(t + 1) & 1][0][0];
            #pragma unroll
            for (int s_m = 0; s_m < 2; ++s_m)
                #pragma unroll
                for (int sn = 0; sn < 2; ++sn)
                    #pragma unroll
                    for (int j = 0; j < 2; ++j) {
                        float4 p = *(float4*)(red + (((s_m*2 + sn)*2 + j)*512) + lane*16);
                        const float* a = acc[s_m][sn][j];
                        const int lcol = wn + sn*16 + j*8 + 2*thr4;
                        const int col = h_base + lcol;
                        float bl  = bias_s[lcol];
                        float bh2 = bias_s[lcol + 1];
                        const int r = b_base + wm + s_m*16 + grp;
                        __half2 v0 = __floats2half2_rn(tanh_fast(a[0] + p.x + bl),
                                                       tanh_fast(a[1] + p.y + bh2));
                        __half2 v1 = __floats2half2_rn(tanh_fast(a[2] + p.z + bl),
                                                       tanh_fast(a[3] + p.w + bh2));
                        *(__half2*)&hdst[(size_t)r*HH + col]     = v0;
                        *(__half2*)&hdst[(size_t)(r+8)*HH + col] = v1;
                    }
        }

        // ---- arrive: release fence by one thread after CTA-wide sync ----
        __syncthreads();
        if (tid == 0) { __threadfence(); atomicAdd(&g_bar[t][ib], 1u); }
    }

    // ---- wait for final h of our ib-group (owns rows 4cta..4cta+3) ----
    if (tid == 0) {
        if (alive) {
            unsigned spins = 0;
            while (*((volatile unsigned*)&g_bar[TT-1][ib]) < IBW) {
                if (++spins >= SPIN_BOUND) { alive = false; break; }
                __nanosleep(8);
            }
        }
        __threadfence();
    }
    __syncthreads();

    // ---- output: o = h_final @ Why^T + by, softmax (4 batch rows per CTA) ----
    float* logits = (float*)sm;
    const __half* hf = &g_h[0][0][0];      // TT even -> final h in buffer 0
    for (int d = warp; d < 4*DOUT; d += 8) {
        int row = d / DOUT, col = d % DOUT;
        int b = 4*cta + row;
        const __half* hp = hf + (size_t)b*HH;
        const float* wpw = Why + (size_t)col*HH;
        float s = 0.f;
        for (int k = lane; k < HH; k += 32)
            s += __half2float(hp[k]) * wpw[k];
        #pragma unroll
        for (int o = 16; o; o >>= 1) s += __shfl_down_sync(0xffffffffu, s, o);
        if (lane == 0) logits[d] = s + by[col];
    }
    __syncthreads();
    if (tid < 4) {
        int b = 4*cta + tid;
        float mx = -1e30f;
        for (int c = 0; c < DOUT; ++c) mx = fmaxf(mx, logits[tid*DOUT + c]);
        float e[DOUT], sum = 0.f;
        for (int c = 0; c < DOUT; ++c) { e[c] = expf(logits[tid*DOUT + c] - mx); sum += e[c]; }
        float inv = 1.f / sum;
        for (int c = 0; c < DOUT; ++c) out[b*DOUT + c] = e[c]*inv;
    }
}

extern "C" void kernel_launch(void* const* d_in, const int* in_sizes, int n_in,
                              void* d_out, int out_size) {
    const float* x   = (const float*)d_in[0];
    const float* Whx = (const float*)d_in[1];
    const float* Whh = (const float*)d_in[2];
    const float* bh  = (const float*)d_in[3];
    const float* Why = (const float*)d_in[4];
    const float* by  = (const float*)d_in[5];
    float* out = (float*)d_out;

    cudaFuncSetAttribute(rnn_hmma_kernel,
                         cudaFuncAttributeMaxDynamicSharedMemorySize, SMEM_BYTES);

    rnn_init_kernel<<<4096, 256>>>(x);
    rnn_hmma_kernel<<<GRID, NTH, SMEM_BYTES>>>(Whh, Whx, bh, Why, by, out);
}